// round 11
// baseline (speedup 1.0000x reference)
#include <cuda_runtime.h>
#include <cuda_fp16.h>
#include <cstdint>

#define B_    16
#define C_    192
#define HW_   4096
#define NOUT  (C_*C_)
#define NROWS 10240            // 160 positions x 64 image rows

__device__ float g_sums[80];
__device__ int   g_cnt[80];
__device__ int   g_bar;
// fp16 variants: v=0 -> dx=-1, v=1 -> dx=0, v=2 -> dx=+1 (edge-clamped)
__device__ __half g_xh[(size_t)3 * B_ * C_ * HW_];

// ---------------------------------------------------------------------------
__device__ __forceinline__ uint32_t smem_u32(const void* p) {
    uint32_t a;
    asm("{ .reg .u64 t; cvta.to.shared.u64 t, %1; cvt.u32.u64 %0, t; }" : "=r"(a) : "l"(p));
    return a;
}
__device__ __forceinline__ void cp_async16(uint32_t dst, const void* src) {
    asm volatile("cp.async.cg.shared.global [%0], [%1], 16;" :: "r"(dst), "l"(src) : "memory");
}
__device__ __forceinline__ void cp_commit() {
    asm volatile("cp.async.commit_group;" ::: "memory");
}
template <int N>
__device__ __forceinline__ void cp_wait() {
    asm volatile("cp.async.wait_group %0;" :: "n"(N) : "memory");
}
__device__ __forceinline__ void ldsm4(uint32_t* r, uint32_t addr) {
    asm volatile("ldmatrix.sync.aligned.m8n8.x4.shared.b16 {%0,%1,%2,%3}, [%4];"
                 : "=r"(r[0]), "=r"(r[1]), "=r"(r[2]), "=r"(r[3]) : "r"(addr));
}
__device__ __forceinline__ void mma16(float* d, const uint32_t* a, const uint32_t* b) {
    asm volatile("mma.sync.aligned.m16n8k16.row.col.f32.f16.f16.f32 "
                 "{%0,%1,%2,%3}, {%4,%5,%6,%7}, {%8,%9}, {%0,%1,%2,%3};"
                 : "+f"(d[0]), "+f"(d[1]), "+f"(d[2]), "+f"(d[3])
                 : "r"(a[0]), "r"(a[1]), "r"(a[2]), "r"(a[3]), "r"(b[0]), "r"(b[1]));
}
__device__ __forceinline__ uint32_t h2(float lo, float hi) {
    // upper = hi, lower = lo  (== __floats2half2_rn(lo, hi))
    uint32_t r;
    asm("cvt.rn.f16x2.f32 %0, %1, %2;" : "=r"(r) : "f"(hi), "f"(lo));
    return r;
}

// ---------------------------------------------------------------------------
// prep (fused zero-init): 8 floats/thread, neighbors via shuffle,
// one STG.128 per variant. Also zeros out[], norm counters, barrier.
// ---------------------------------------------------------------------------
__global__ __launch_bounds__(256) void cofe_prep(const float* __restrict__ x,
                                                 float* __restrict__ out) {
    int idx = blockIdx.x * 256 + threadIdx.x;     // 6144*256 = 1,572,864
    if (idx < 737280)
        reinterpret_cast<float4*>(out)[idx] = make_float4(0.f, 0.f, 0.f, 0.f);
    if (idx < 80) { g_sums[idx] = 0.f; g_cnt[idx] = 0; }
    if (idx == 0) g_bar = 0;

    int r = idx >> 3;            // row = (b*C + c)*64 + y
    int t = idx & 7;             // oct: floats [8t, 8t+8)
    const float4* src = reinterpret_cast<const float4*>(x + (size_t)r * 64) + t * 2;
    float4 v1 = src[0], v2 = src[1];

    // neighbors within the 8-thread row group
    float pv = __shfl_up_sync(0xffffffffu,  v2.w, 1);   // x[8t-1]
    float nx = __shfl_down_sync(0xffffffffu, v1.x, 1);  // x[8t+8]
    if (t == 0) pv = v1.x;       // left edge clamp
    if (t == 7) nx = v2.w;       // right edge clamp

    const size_t VS = (size_t)B_ * C_ * HW_;
    size_t o = (size_t)r * 64 + t * 8;

    uint32_t e0 = h2(v1.x, v1.y), e1 = h2(v1.z, v1.w);
    uint32_t e2 = h2(v2.x, v2.y), e3 = h2(v2.z, v2.w);
    uint32_t m0 = h2(pv,  v1.x),  m1 = h2(v1.y, v1.z);
    uint32_t m2 = h2(v1.w, v2.x), m3 = h2(v2.y, v2.z);
    uint32_t p3 = h2(v2.w, nx);

    *reinterpret_cast<uint4*>(g_xh + o)          = make_uint4(m0, m1, m2, m3); // dx=-1
    *reinterpret_cast<uint4*>(g_xh + VS + o)     = make_uint4(e0, e1, e2, e3); // dx=0
    *reinterpret_cast<uint4*>(g_xh + 2*VS + o)   = make_uint4(m1, m2, m3, p3); // dx=+1
}

// ---------------------------------------------------------------------------
// Persistent mega-kernel: GEMM rows -> global barrier -> fused norm.
// grid = 2*SMs (all resident: 72KB smem/CTA -> occ 2 guaranteed).
// ---------------------------------------------------------------------------
#define STAGE_B 36864
#define SM_REQ  (2 * STAGE_B)

__global__ __launch_bounds__(128, 2)
void cofe_mma(float* __restrict__ out) {
    extern __shared__ char smraw[];
    const uint32_t smem = smem_u32(smraw);

    const int tid  = threadIdx.x;
    const int lane = tid & 31;
    const int wid  = tid >> 5;
    const int wr   = wid >> 1;
    const int wc   = wid & 1;

    const int G  = gridDim.x;
    const int r0 = (int)(((long long)blockIdx.x * NROWS) / G);
    const int r1 = (int)(((long long)(blockIdx.x + 1) * NROWS) / G);

    const size_t VS = (size_t)B_ * C_ * HW_;

    const int mrel  = (lane & 7) + ((lane >> 3) & 1) * 8;
    const int kcsA  = lane >> 4;
    const int nrel  = (lane & 7) + (lane >> 4) * 8;
    const int kcsB  = (lane >> 3) & 1;
    const int klane = lane & 7;

    float acc[3][12][4];
#pragma unroll
    for (int i = 0; i < 3; i++)
#pragma unroll
        for (int j = 0; j < 12; j++)
#pragma unroll
            for (int r = 0; r < 4; r++) acc[i][j][r] = 0.f;

    auto fillA = [&](int st, int rr) {
        int pos = rr >> 6, y = rr & 63;
        int gg  = pos >> 1, mtv = pos & 1;
        int bb  = gg / 5;
        const __half* xAh = g_xh + VS + ((size_t)(bb * C_ + mtv * 96)) * HW_;
        uint32_t smA = smem + st * STAGE_B;
#pragma unroll
        for (int i = 0; i < 6; i++) {
            int q = tid + 128 * i;
            int m = q >> 3, t = q & 7;
            uint32_t dst = smA + m * 128 + ((t ^ (m & 7)) << 4);
            cp_async16(dst, xAh + (size_t)m * HW_ + (y << 6) + t * 8);
        }
    };
    auto fillB = [&](int st, int rr) {
        int pos = rr >> 6, y = rr & 63;
        int gg  = pos >> 1;
        int bb  = gg / 5, off = gg % 5;
        int dyv = (off < 3) ? -1 : 0;
        int dxv = (off < 3) ? (off - 1) : ((off == 3) ? -1 : 0);
        int py  = y + dyv; if (py < 0) py = 0;
        const __half* xBh = g_xh + (size_t)(dxv + 1) * VS + (size_t)(bb * C_) * HW_;
        uint32_t smB = smem + st * STAGE_B + 12288;
#pragma unroll
        for (int i = 0; i < 12; i++) {
            int q = i * 128 + tid;
            int n = q >> 3, t = q & 7;
            uint32_t dst = smB + n * 128 + ((t ^ (n & 7)) << 4);
            cp_async16(dst, xBh + (size_t)n * HW_ + (py << 6) + t * 8);
        }
    };
    auto flush = [&](int pos) {
        int gg  = pos >> 1, mtv = pos & 1;
        int cA0 = mtv * 96;
        float* po = out + (size_t)gg * NOUT;
        const int rA = lane >> 2, cB = (lane & 3) * 2;
#pragma unroll
        for (int i = 0; i < 3; i++) {
            int c0 = cA0 + wr * 48 + i * 16 + rA;
#pragma unroll
            for (int j = 0; j < 12; j++) {
                int d0 = wc * 96 + j * 8 + cB;
                atomicAdd(po + (size_t)c0 * C_ + d0,     acc[i][j][0]);
                atomicAdd(po + (size_t)c0 * C_ + d0 + 1, acc[i][j][1]);
                atomicAdd(po + (size_t)(c0 + 8) * C_ + d0,     acc[i][j][2]);
                atomicAdd(po + (size_t)(c0 + 8) * C_ + d0 + 1, acc[i][j][3]);
                acc[i][j][0] = 0.f; acc[i][j][1] = 0.f;
                acc[i][j][2] = 0.f; acc[i][j][3] = 0.f;
            }
        }
    };

    // ---- GEMM phase ----
    fillB(0, r0);
    fillA(0, r0);
    cp_commit();

    for (int r = r0; r < r1; r++) {
        int st = (r - r0) & 1;
        __syncthreads();
        if (r + 1 < r1) {
            fillB(st ^ 1, r + 1);
            fillA(st ^ 1, r + 1);
            cp_commit();
            cp_wait<1>();
        } else {
            cp_wait<0>();
        }
        __syncthreads();

        uint32_t smA = smem + st * STAGE_B;
        uint32_t smB = smA + 12288;
        uint32_t aA0 = smA + (wr * 48 + mrel) * 128;
        uint32_t aB0 = smB + (wc * 96 + nrel) * 128;

#pragma unroll
        for (int ks = 0; ks < 4; ks++) {
            uint32_t af[3][4], bf[6][4];
#pragma unroll
            for (int i = 0; i < 3; i++)
                ldsm4(af[i], aA0 + i * (16 * 128) + (((ks * 2 + kcsA) ^ klane) << 4));
#pragma unroll
            for (int t = 0; t < 6; t++)
                ldsm4(bf[t], aB0 + t * (16 * 128) + (((ks * 2 + kcsB) ^ klane) << 4));
#pragma unroll
            for (int i = 0; i < 3; i++)
#pragma unroll
                for (int j = 0; j < 12; j++)
                    mma16(acc[i][j], af[i], &bf[j >> 1][(j & 1) * 2]);
        }

        if ((r & 63) == 63 || r == r1 - 1)
            flush(r >> 6);
    }

    // ---- global barrier: all flushes visible ----
    __syncthreads();
    if (tid == 0) {
        __threadfence();
        atomicAdd(&g_bar, 1);
        while (atomicAdd(&g_bar, 0) < G) { }
        __threadfence();
    }
    __syncthreads();

    // ---- norm phase: segments [s0, s1) of 640; 4608 floats each ----
    const int s0 = (int)(((long long)blockIdx.x * 640) / G);
    const int s1 = (int)(((long long)(blockIdx.x + 1) * 640) / G);
    __shared__ float red[4];
    __shared__ float s_scale;

    // pass A: arrive for ALL my segments first (deadlock-free ordering)
    for (int seg = s0; seg < s1; seg++) {
        int gg = seg >> 3;
        const float4* p = reinterpret_cast<const float4*>(
            out + (size_t)gg * NOUT + (seg & 7) * 4608);
        float ss = 0.f;
#pragma unroll
        for (int i = 0; i < 9; i++) {
            float4 v = p[tid + 128 * i];
            ss += v.x * v.x + v.y * v.y + v.z * v.z + v.w * v.w;
        }
#pragma unroll
        for (int d = 16; d > 0; d >>= 1) ss += __shfl_xor_sync(0xffffffffu, ss, d);
        if ((tid & 31) == 0) red[tid >> 5] = ss;
        __syncthreads();
        if (tid == 0) {
            atomicAdd(&g_sums[gg], red[0] + red[1] + red[2] + red[3]);
            __threadfence();
            atomicAdd(&g_cnt[gg], 1);
        }
        __syncthreads();
    }
    // pass B: spin + scale
    for (int seg = s0; seg < s1; seg++) {
        int gg = seg >> 3;
        float4* p = reinterpret_cast<float4*>(
            out + (size_t)gg * NOUT + (seg & 7) * 4608);
        if (tid == 0) {
            while (atomicAdd(&g_cnt[gg], 0) < 8) { }
            __threadfence();
            s_scale = 1.0f / fmaxf(sqrtf(atomicAdd(&g_sums[gg], 0.0f)), 1e-12f);
        }
        __syncthreads();
        const float scale = s_scale;
#pragma unroll
        for (int i = 0; i < 9; i++) {
            float4 v = p[tid + 128 * i];
            v.x *= scale; v.y *= scale; v.z *= scale; v.w *= scale;
            p[tid + 128 * i] = v;
        }
        __syncthreads();
    }
}

// ---------------------------------------------------------------------------
extern "C" void kernel_launch(void* const* d_in, const int* in_sizes, int n_in,
                              void* d_out, int out_size) {
    const float* x = (const float*)d_in[0];
    float* out = (float*)d_out;

    int sms = 0;
    cudaDeviceGetAttribute(&sms, cudaDevAttrMultiProcessorCount, 0);
    if (sms <= 0) sms = 148;
    int grid = 2 * sms;

    cofe_prep<<<6144, 256>>>(x, out);
    cudaFuncSetAttribute(cofe_mma, cudaFuncAttributeMaxDynamicSharedMemorySize, SM_REQ);
    cofe_mma<<<grid, 128, SM_REQ>>>(out);
}

// round 12
// speedup vs baseline: 1.2854x; 1.2854x over previous
#include <cuda_runtime.h>
#include <cuda_fp16.h>
#include <cstdint>

#define B_    16
#define C_    192
#define HW_   4096
#define NOUT  (C_*C_)
#define NROWS 10240            // 160 positions x 64 image rows

__device__ float g_sums[80];
__device__ int   g_cnt[80];
// fp16 variants: v=0 -> dx=-1, v=1 -> dx=0, v=2 -> dx=+1 (edge-clamped)
__device__ __half g_xh[(size_t)3 * B_ * C_ * HW_];

// ---------------------------------------------------------------------------
__device__ __forceinline__ uint32_t smem_u32(const void* p) {
    uint32_t a;
    asm("{ .reg .u64 t; cvta.to.shared.u64 t, %1; cvt.u32.u64 %0, t; }" : "=r"(a) : "l"(p));
    return a;
}
__device__ __forceinline__ void cp_async16(uint32_t dst, const void* src) {
    asm volatile("cp.async.cg.shared.global [%0], [%1], 16;" :: "r"(dst), "l"(src) : "memory");
}
__device__ __forceinline__ void cp_commit() {
    asm volatile("cp.async.commit_group;" ::: "memory");
}
template <int N>
__device__ __forceinline__ void cp_wait() {
    asm volatile("cp.async.wait_group %0;" :: "n"(N) : "memory");
}
__device__ __forceinline__ void ldsm4(uint32_t* r, uint32_t addr) {
    asm volatile("ldmatrix.sync.aligned.m8n8.x4.shared.b16 {%0,%1,%2,%3}, [%4];"
                 : "=r"(r[0]), "=r"(r[1]), "=r"(r[2]), "=r"(r[3]) : "r"(addr));
}
__device__ __forceinline__ void mma16(float* d, const uint32_t* a, const uint32_t* b) {
    asm volatile("mma.sync.aligned.m16n8k16.row.col.f32.f16.f16.f32 "
                 "{%0,%1,%2,%3}, {%4,%5,%6,%7}, {%8,%9}, {%0,%1,%2,%3};"
                 : "+f"(d[0]), "+f"(d[1]), "+f"(d[2]), "+f"(d[3])
                 : "r"(a[0]), "r"(a[1]), "r"(a[2]), "r"(a[3]), "r"(b[0]), "r"(b[1]));
}
__device__ __forceinline__ uint32_t h2(float lo, float hi) {
    uint32_t r;
    asm("cvt.rn.f16x2.f32 %0, %1, %2;" : "=r"(r) : "f"(hi), "f"(lo));
    return r;
}

// ---------------------------------------------------------------------------
// prep (fused zero-init): 8 floats/thread, neighbors via shuffle,
// one STG.128 per variant. Also zeros out[] and norm counters.
// ---------------------------------------------------------------------------
__global__ __launch_bounds__(256) void cofe_prep(const float* __restrict__ x,
                                                 float* __restrict__ out) {
    int idx = blockIdx.x * 256 + threadIdx.x;     // 6144*256 = 1,572,864
    if (idx < 737280)
        reinterpret_cast<float4*>(out)[idx] = make_float4(0.f, 0.f, 0.f, 0.f);
    if (idx < 80) { g_sums[idx] = 0.f; g_cnt[idx] = 0; }

    int r = idx >> 3;            // row = (b*C + c)*64 + y
    int t = idx & 7;             // oct: floats [8t, 8t+8)
    const float4* src = reinterpret_cast<const float4*>(x + (size_t)r * 64) + t * 2;
    float4 v1 = src[0], v2 = src[1];

    float pv = __shfl_up_sync(0xffffffffu,  v2.w, 1);   // x[8t-1]
    float nx = __shfl_down_sync(0xffffffffu, v1.x, 1);  // x[8t+8]
    if (t == 0) pv = v1.x;       // left edge clamp
    if (t == 7) nx = v2.w;       // right edge clamp

    const size_t VS = (size_t)B_ * C_ * HW_;
    size_t o = (size_t)r * 64 + t * 8;

    uint32_t e0 = h2(v1.x, v1.y), e1 = h2(v1.z, v1.w);
    uint32_t e2 = h2(v2.x, v2.y), e3 = h2(v2.z, v2.w);
    uint32_t m0 = h2(pv,  v1.x),  m1 = h2(v1.y, v1.z);
    uint32_t m2 = h2(v1.w, v2.x), m3 = h2(v2.y, v2.z);
    uint32_t p3 = h2(v2.w, nx);

    *reinterpret_cast<uint4*>(g_xh + o)        = make_uint4(m0, m1, m2, m3); // dx=-1
    *reinterpret_cast<uint4*>(g_xh + VS + o)   = make_uint4(e0, e1, e2, e3); // dx=0
    *reinterpret_cast<uint4*>(g_xh + 2*VS + o) = make_uint4(m1, m2, m3, p3); // dx=+1
}

// ---------------------------------------------------------------------------
// Persistent GEMM (round-10 structure, unfused): grid = 2*SMs, one wave.
// Row rr: pos = rr>>6 (g = pos>>1, mt = pos&1), y = rr&63.
// Double-buffered cp.async fills; 4x m16n8k16 per row; warp tile 48x96.
// Flush acc via atomics at position boundaries.
// ---------------------------------------------------------------------------
#define STAGE_B 36864
#define SM_REQ  (2 * STAGE_B)

__global__ __launch_bounds__(128, 2)
void cofe_mma(float* __restrict__ out) {
    extern __shared__ char smraw[];
    const uint32_t smem = smem_u32(smraw);

    const int tid  = threadIdx.x;
    const int lane = tid & 31;
    const int wid  = tid >> 5;
    const int wr   = wid >> 1;
    const int wc   = wid & 1;

    const int G  = gridDim.x;
    const int r0 = (int)(((long long)blockIdx.x * NROWS) / G);
    const int r1 = (int)(((long long)(blockIdx.x + 1) * NROWS) / G);

    const size_t VS = (size_t)B_ * C_ * HW_;

    const int mrel  = (lane & 7) + ((lane >> 3) & 1) * 8;
    const int kcsA  = lane >> 4;
    const int nrel  = (lane & 7) + (lane >> 4) * 8;
    const int kcsB  = (lane >> 3) & 1;
    const int klane = lane & 7;

    float acc[3][12][4];
#pragma unroll
    for (int i = 0; i < 3; i++)
#pragma unroll
        for (int j = 0; j < 12; j++)
#pragma unroll
            for (int r = 0; r < 4; r++) acc[i][j][r] = 0.f;

    auto fillA = [&](int st, int rr) {
        int pos = rr >> 6, y = rr & 63;
        int gg  = pos >> 1, mtv = pos & 1;
        int bb  = gg / 5;
        const __half* xAh = g_xh + VS + ((size_t)(bb * C_ + mtv * 96)) * HW_;
        uint32_t smA = smem + st * STAGE_B;
#pragma unroll
        for (int i = 0; i < 6; i++) {
            int q = tid + 128 * i;
            int m = q >> 3, t = q & 7;
            uint32_t dst = smA + m * 128 + ((t ^ (m & 7)) << 4);
            cp_async16(dst, xAh + (size_t)m * HW_ + (y << 6) + t * 8);
        }
    };
    auto fillB = [&](int st, int rr) {
        int pos = rr >> 6, y = rr & 63;
        int gg  = pos >> 1;
        int bb  = gg / 5, off = gg % 5;
        int dyv = (off < 3) ? -1 : 0;
        int dxv = (off < 3) ? (off - 1) : ((off == 3) ? -1 : 0);
        int py  = y + dyv; if (py < 0) py = 0;
        const __half* xBh = g_xh + (size_t)(dxv + 1) * VS + (size_t)(bb * C_) * HW_;
        uint32_t smB = smem + st * STAGE_B + 12288;
#pragma unroll
        for (int i = 0; i < 12; i++) {
            int q = i * 128 + tid;
            int n = q >> 3, t = q & 7;
            uint32_t dst = smB + n * 128 + ((t ^ (n & 7)) << 4);
            cp_async16(dst, xBh + (size_t)n * HW_ + (py << 6) + t * 8);
        }
    };
    auto flush = [&](int pos) {
        int gg  = pos >> 1, mtv = pos & 1;
        int cA0 = mtv * 96;
        float* po = out + (size_t)gg * NOUT;
        const int rA = lane >> 2, cB = (lane & 3) * 2;
#pragma unroll
        for (int i = 0; i < 3; i++) {
            int c0 = cA0 + wr * 48 + i * 16 + rA;
#pragma unroll
            for (int j = 0; j < 12; j++) {
                int d0 = wc * 96 + j * 8 + cB;
                atomicAdd(po + (size_t)c0 * C_ + d0,     acc[i][j][0]);
                atomicAdd(po + (size_t)c0 * C_ + d0 + 1, acc[i][j][1]);
                atomicAdd(po + (size_t)(c0 + 8) * C_ + d0,     acc[i][j][2]);
                atomicAdd(po + (size_t)(c0 + 8) * C_ + d0 + 1, acc[i][j][3]);
                acc[i][j][0] = 0.f; acc[i][j][1] = 0.f;
                acc[i][j][2] = 0.f; acc[i][j][3] = 0.f;
            }
        }
    };

    // ---- prologue ----
    fillB(0, r0);
    fillA(0, r0);
    cp_commit();

    // ---- persistent row loop ----
    for (int r = r0; r < r1; r++) {
        int st = (r - r0) & 1;
        __syncthreads();
        if (r + 1 < r1) {
            fillB(st ^ 1, r + 1);
            fillA(st ^ 1, r + 1);
            cp_commit();
            cp_wait<1>();
        } else {
            cp_wait<0>();
        }
        __syncthreads();

        uint32_t smA = smem + st * STAGE_B;
        uint32_t smB = smA + 12288;
        uint32_t aA0 = smA + (wr * 48 + mrel) * 128;
        uint32_t aB0 = smB + (wc * 96 + nrel) * 128;

#pragma unroll
        for (int ks = 0; ks < 4; ks++) {
            uint32_t af[3][4], bf[6][4];
#pragma unroll
            for (int i = 0; i < 3; i++)
                ldsm4(af[i], aA0 + i * (16 * 128) + (((ks * 2 + kcsA) ^ klane) << 4));
#pragma unroll
            for (int t = 0; t < 6; t++)
                ldsm4(bf[t], aB0 + t * (16 * 128) + (((ks * 2 + kcsB) ^ klane) << 4));
#pragma unroll
            for (int i = 0; i < 3; i++)
#pragma unroll
                for (int j = 0; j < 12; j++)
                    mma16(acc[i][j], af[i], &bf[j >> 1][(j & 1) * 2]);
        }

        if ((r & 63) == 63 || r == r1 - 1)
            flush(r >> 6);
    }
}

// ---------------------------------------------------------------------------
// fused norm: 8 blocks per g (grid 640, all resident -> spin barrier safe).
// ---------------------------------------------------------------------------
__global__ __launch_bounds__(256) void cofe_norm(float* __restrict__ out) {
    const int g = blockIdx.x >> 3, seg = blockIdx.x & 7;
    float4* p = reinterpret_cast<float4*>(out + (size_t)g * NOUT + seg * 4608);
    const int tid = threadIdx.x;

    float ss = 0.f;
#pragma unroll
    for (int i = tid; i < 1152; i += 256) {
        float4 v = p[i];
        ss += v.x * v.x + v.y * v.y + v.z * v.z + v.w * v.w;
    }
    __shared__ float red[8];
    __shared__ float s_scale;
#pragma unroll
    for (int d = 16; d > 0; d >>= 1) ss += __shfl_xor_sync(0xffffffffu, ss, d);
    if ((tid & 31) == 0) red[tid >> 5] = ss;
    __syncthreads();
    if (tid == 0) {
        float v = red[0] + red[1] + red[2] + red[3] +
                  red[4] + red[5] + red[6] + red[7];
        atomicAdd(&g_sums[g], v);
        __threadfence();
        atomicAdd(&g_cnt[g], 1);
        while (atomicAdd(&g_cnt[g], 0) < 8) { }
        __threadfence();
        float tot = atomicAdd(&g_sums[g], 0.0f);
        s_scale = 1.0f / fmaxf(sqrtf(tot), 1e-12f);
    }
    __syncthreads();
    const float scale = s_scale;

#pragma unroll
    for (int i = tid; i < 1152; i += 256) {
        float4 v = p[i];
        v.x *= scale; v.y *= scale; v.z *= scale; v.w *= scale;
        p[i] = v;
    }
}

// ---------------------------------------------------------------------------
extern "C" void kernel_launch(void* const* d_in, const int* in_sizes, int n_in,
                              void* d_out, int out_size) {
    const float* x = (const float*)d_in[0];
    float* out = (float*)d_out;

    int sms = 0;
    cudaDeviceGetAttribute(&sms, cudaDevAttrMultiProcessorCount, 0);
    if (sms <= 0) sms = 148;
    int grid = 2 * sms;

    cofe_prep<<<6144, 256>>>(x, out);
    cudaFuncSetAttribute(cofe_mma, cudaFuncAttributeMaxDynamicSharedMemorySize, SM_REQ);
    cofe_mma<<<grid, 128, SM_REQ>>>(out);
    cofe_norm<<<640, 256>>>(out);
}